// round 15
// baseline (speedup 1.0000x reference)
#include <cuda_runtime.h>
#include <cuda_fp16.h>
#include <cstdint>

// ---------------------------------------------------------------------------
// QKVProjectedLinear, single-launch, decoupled two-stage through L2:
//   U = B @ Ws^T (CTAs 0..143), V/G on tail CTAs 128..147
//   stage 1: t1 = fp16(x) @ fp16(A_all) -> g_t1 (global fp16, L2-resident),
//            per-row-tile release flag
//   stage 2: 384 jobs (row-tile x kq), statically spread over ALL 148 CTAs
// 148 CTAs x 384 thr. warps 0-7 consumers, 8-11 producers.
// ---------------------------------------------------------------------------

#define K3 3
#define DL 1024
#define DS 768
#define RK 64
#define NJ 192
#define DOUT 3072
#define NWORK 128
#define NCTA 148
#define NU 144
#define NP0 20
#define NTHR 384
#define NJOBS2 384

// ------------------------- device scratch ----------------------------------
__device__ __align__(16) float g_U[K3*RK*DS];
__device__ __align__(16) float g_Vp[K3*4*RK*RK];
__device__ __align__(16) __half g_Af[DL*NJ];             // A_all fp16 [1024,192]
__device__ __align__(16) __half g_G[K3*RK*DL];           // G fp16 [3,64,1024]
__device__ __align__(16) __half g_t1[16384*NJ];          // t1 fp16 [16384,192]
__device__ int c_A, c_U, c_V, c_G;
__device__ int t1_ready[NWORK];

__device__ __forceinline__ uint32_t pack2h(__half a, __half b){
    __half2 t; t.x = a; t.y = b;
    return *reinterpret_cast<uint32_t*>(&t);
}

// ------------------------- sync helpers ------------------------------------
__device__ __forceinline__ void flag_inc(int* f){
    __syncthreads();
    __threadfence();
    if (threadIdx.x == 0)
        asm volatile("red.release.gpu.global.add.s32 [%0], 1;" :: "l"(f) : "memory");
}
__device__ __forceinline__ void flag_wait(int* f, int thr){   // CTA-wide
    if (threadIdx.x == 0){
        int v;
        do {
            asm volatile("ld.acquire.gpu.global.s32 %0, [%1];" : "=r"(v) : "l"(f));
            if (v < thr) __nanosleep(128);
        } while (v < thr);
    }
    __syncthreads();
}
__device__ __forceinline__ void prod_wait(const int* f, int thr){ // producer warps
    if (threadIdx.x == 256){
        int v;
        do {
            asm volatile("ld.acquire.gpu.global.s32 %0, [%1];" : "=r"(v) : "l"(f));
            if (v < thr) __nanosleep(128);
        } while (v < thr);
    }
    asm volatile("bar.sync 2, 128;" ::: "memory");
}

__device__ __forceinline__ uint32_t smem_u32(const void* p){
    uint32_t a;
    asm("{ .reg .u64 t; cvta.to.shared.u64 t, %1; cvt.u32.u64 %0, t; }" : "=r"(a) : "l"(p));
    return a;
}
#define MBAR_INIT(mb, c)  asm volatile("mbarrier.init.shared.b64 [%0], %1;" :: "r"(mb), "r"(c) : "memory")
#define MBAR_ARRIVE(mb)   asm volatile("mbarrier.arrive.shared.b64 _, [%0];" :: "r"(mb) : "memory")
__device__ __forceinline__ void mbar_wait(uint32_t mb, uint32_t parity){
    asm volatile(
        "{\n\t.reg .pred P;\n\t"
        "W%=:\n\t"
        "mbarrier.try_wait.parity.acquire.cta.shared::cta.b64 P, [%0], %1, 0x989680;\n\t"
        "@!P bra W%=;\n\t}"
        :: "r"(mb), "r"(parity) : "memory");
}

__device__ __forceinline__ void cpa16(uint32_t dst, const void* src){
    asm volatile("cp.async.cg.shared.global [%0], [%1], 16;" :: "r"(dst), "l"(src) : "memory");
}
#define CPA_COMMIT() asm volatile("cp.async.commit_group;" ::: "memory")
#define CPA_WAIT0()  asm volatile("cp.async.wait_group 0;" ::: "memory")

// ------------------------- mma helpers --------------------------------------
__device__ __forceinline__ void ldsm4(uint32_t* r, const void* p){
    uint32_t a = smem_u32(p);
    asm volatile("ldmatrix.sync.aligned.m8n8.x4.shared.b16 {%0,%1,%2,%3}, [%4];"
        : "=r"(r[0]), "=r"(r[1]), "=r"(r[2]), "=r"(r[3]) : "r"(a));
}
__device__ __forceinline__ void ldsm4t(uint32_t* r, const void* p){
    uint32_t a = smem_u32(p);
    asm volatile("ldmatrix.sync.aligned.m8n8.x4.trans.shared.b16 {%0,%1,%2,%3}, [%4];"
        : "=r"(r[0]), "=r"(r[1]), "=r"(r[2]), "=r"(r[3]) : "r"(a));
}
__device__ __forceinline__ void mma_f16(float* c, const uint32_t* a, const uint32_t* b){
    asm volatile("mma.sync.aligned.m16n8k16.row.col.f32.f16.f16.f32 "
        "{%0,%1,%2,%3}, {%4,%5,%6,%7}, {%8,%9}, {%0,%1,%2,%3};"
        : "+f"(c[0]), "+f"(c[1]), "+f"(c[2]), "+f"(c[3])
        : "r"(a[0]), "r"(a[1]), "r"(a[2]), "r"(a[3]), "r"(b[0]), "r"(b[1]));
}

// ------------------------- phase-0 jobs -------------------------------------
// U[k,r,s] = sum_t B[k,r,t]*W[(k*768+s),t].  Job: 64 rows x 16 s-cols.
__device__ void p0U16_job(int k, int s0, char* smem,
                          const float* __restrict__ B, const float* __restrict__ W){
    float* Bt = (float*)smem;          // [64][65]
    float* Wt = Bt + 64*65;            // [16][65]
    const int tid = threadIdx.x;
    const int lane = tid & 31, w = tid >> 5;
    float acc[2][4] = {};
    for (int tc = 0; tc < 12; tc++){
        const int t0 = tc*64;
        __syncthreads();
        #pragma unroll
        for (int i = 0; i < 11; i++){
            int idx = tid + i*NTHR;
            if (idx < 4096){
                int r = idx >> 6, t = idx & 63;
                Bt[r*65 + t] = B[(k*64 + r)*DS + t0 + t];
            }
        }
        #pragma unroll
        for (int i = 0; i < 3; i++){
            int idx = tid + i*NTHR;
            if (idx < 1024){
                int s = idx >> 6, t = idx & 63;
                Wt[s*65 + t] = W[(size_t)(k*DS + s0 + s)*DS + t0 + t];
            }
        }
        __syncthreads();
        if (w < 4){
            #pragma unroll 8
            for (int t = 0; t < 64; t++){
                float a0 = Bt[lane*65 + t];
                float a1 = Bt[(lane + 32)*65 + t];
                #pragma unroll
                for (int j = 0; j < 4; j++){
                    float b = Wt[(w*4 + j)*65 + t];
                    acc[0][j] += a0*b;
                    acc[1][j] += a1*b;
                }
            }
        }
    }
    if (w < 4){
        #pragma unroll
        for (int j = 0; j < 4; j++){
            g_U[(k*64 + lane)*DS + s0 + w*4 + j]      = acc[0][j];
            g_U[(k*64 + lane + 32)*DS + s0 + w*4 + j] = acc[1][j];
        }
    }
    __syncthreads();   // race fix: don't let non-compute warps leave early
}

__device__ void p0V_job(int k, int sc, char* smem, const float* __restrict__ B){
    float* Us = (float*)smem;          // [64][65]
    float* Bs = Us + 64*65;
    int tid = threadIdx.x;
    float acc[4][4] = {};
    int r0 = (tid & 15)*4, q0 = ((tid >> 4) & 15)*4;
    for (int si = 0; si < 3; si++){
        int s0 = sc*192 + si*64;
        __syncthreads();
        if (tid < 256){
            #pragma unroll
            for (int i = 0; i < 16; i++){
                int idx = tid + (i<<8); int r = idx>>6, s = idx&63;
                Us[r*65 + s] = g_U[(k*64 + r)*DS + s0 + s];
                Bs[r*65 + s] = B[(k*64 + r)*DS + s0 + s];
            }
        }
        __syncthreads();
        if (tid < 256){
            #pragma unroll 4
            for (int s = 0; s < 64; s++){
                float a[4], b[4];
                #pragma unroll
                for (int i = 0; i < 4; i++){ a[i] = Us[(r0+i)*65 + s]; b[i] = Bs[(q0+i)*65 + s]; }
                #pragma unroll
                for (int i = 0; i < 4; i++)
                    #pragma unroll
                    for (int j = 0; j < 4; j++) acc[i][j] += a[i]*b[j];
            }
        }
    }
    if (tid < 256)
        #pragma unroll
        for (int i = 0; i < 4; i++)
            #pragma unroll
            for (int j = 0; j < 4; j++)
                g_Vp[((k*4 + sc)*64 + r0 + i)*64 + q0 + j] = acc[i][j];
    __syncthreads();
}

__device__ void p0G_job(int k, int e0, char* smem, const float* __restrict__ A){
    float* Vs = (float*)smem;          // [64][68]
    float* As = Vs + 64*68;
    int tid = threadIdx.x;
    __syncthreads();
    if (tid < 256){
        #pragma unroll
        for (int i = 0; i < 16; i++){
            int idx = tid + (i<<8); int a = idx>>6, b = idx&63;
            float v = 0.f;
            #pragma unroll
            for (int sc = 0; sc < 4; sc++) v += g_Vp[((k*4 + sc)*64 + a)*64 + b];
            Vs[a*68 + b] = v;
            As[a*68 + b] = A[(size_t)(k*DL + e0 + a)*RK + b];
        }
    }
    __syncthreads();
    if (tid < 256){
        int r0 = (tid & 15)*4, ee = ((tid >> 4) & 15)*4;
        float acc[4][4] = {};
        #pragma unroll 4
        for (int q = 0; q < 64; q++){
            float a[4], b[4];
            #pragma unroll
            for (int i = 0; i < 4; i++){ a[i] = Vs[(r0+i)*68 + q]; b[i] = As[(ee+i)*68 + q]; }
            #pragma unroll
            for (int i = 0; i < 4; i++)
                #pragma unroll
                for (int j = 0; j < 4; j++) acc[i][j] += a[i]*b[j];
        }
        #pragma unroll
        for (int i = 0; i < 4; i++)
            #pragma unroll
            for (int j = 0; j < 4; j++)
                g_G[(size_t)(k*64 + r0 + i)*DL + e0 + ee + j] = __float2half(acc[i][j]);
    }
    __syncthreads();
}

// ------------------------- smem layout --------------------------------------
// stage1: x bufs [s] 2x18432 @0; A bufs [s] 2x25600 @36864 (end 88064)
// stage2: t1 slice [128][72]h = 18432 @0; G bufs [s] 3x17408 @51200 (end 103424)
#define XOFF(s)     ((s)*18432)
#define AOFF(s)     (36864 + (s)*25600)
#define GOFF(s)     (51200 + (s)*17408)
#define SMEM_BYTES  103424
#define XPITCH 72
#define APITCH 200
#define GPITCH 136

__global__ __launch_bounds__(NTHR, 1)
void qkv_main(const float* __restrict__ x, const float* __restrict__ W,
              const float* __restrict__ A, const float* __restrict__ B,
              float* __restrict__ out){
    extern __shared__ char smem[];
    __shared__ __align__(8) uint64_t s_mb[12];  // f1[2] e1[2] f2[3] e2[3] t1f t1e

    const int tid = threadIdx.x;
    const int bid = blockIdx.x;
    const uint32_t sbase = smem_u32(smem);
    const uint32_t f1  = smem_u32(&s_mb[0]);
    const uint32_t e1  = smem_u32(&s_mb[2]);
    const uint32_t f2  = smem_u32(&s_mb[4]);
    const uint32_t e2  = smem_u32(&s_mb[7]);
    const uint32_t t1f = smem_u32(&s_mb[10]);
    const uint32_t t1e = smem_u32(&s_mb[11]);

    if (tid == 0){
        MBAR_INIT(f1,     128); MBAR_INIT(f1 + 8, 128);
        MBAR_INIT(e1,     256); MBAR_INIT(e1 + 8, 256);
        MBAR_INIT(f2,     128); MBAR_INIT(f2 + 8, 128); MBAR_INIT(f2 + 16, 128);
        MBAR_INIT(e2,     256); MBAR_INIT(e2 + 8, 256); MBAR_INIT(e2 + 16, 256);
        MBAR_INIT(t1f,    128); MBAR_INIT(t1e,    256);
    }
    __syncthreads();

    // ===== phase 0a: A conversion (all CTAs) ===============================
    for (int idx = bid*NTHR + tid; idx < K3*DL*RK; idx += NCTA*NTHR){
        int k = idx/(DL*RK); int rem = idx%(DL*RK); int d = rem/RK; int r = rem%RK;
        g_Af[d*NJ + k*RK + r] = __float2half(A[idx]);
    }
    flag_inc(&c_A);

    // ===== phase 0b: U distributed (CTAs 0..143) ===========================
    if (bid < NU){
        p0U16_job(bid/48, (bid%48)*16, smem, B, W);
        flag_inc(&c_U);
    }

    if (bid >= NWORK){
        // ===== phase-0 tail: V then G ======================================
        const int p = bid - NWORK;     // 0..19
        flag_wait(&c_U, NU);
        if (p < 12){
            p0V_job(p/4, p%4, smem, B);
            flag_inc(&c_V);
        }
        flag_wait(&c_V, 12);
        for (int j = p; j < 48; j += NP0)
            p0G_job(j/16, (j%16)*64, smem, A);
        flag_inc(&c_G);
    } else {
        // ===== stage 1: t1 tile -> global ==================================
        const int row0 = bid * 128;
        if (tid >= 256){
            const int tp = tid - 256;
            prod_wait(&c_A, NCTA);
            for (int ci = 0; ci < 16; ci++){
                const int s = ci & 1;
                const uint32_t ph = (ci >> 1) & 1;
                mbar_wait(e1 + s*8, ph ^ 1);
                {
                    const char* src = (const char*)g_Af + (size_t)ci*24576;
                    uint32_t dst = sbase + AOFF(s);
                    #pragma unroll
                    for (int i = 0; i < 12; i++){
                        int j = tp + (i << 7);
                        int r = j / 24, c = j % 24;
                        cpa16(dst + r*400 + c*16, src + j*16);
                    }
                    CPA_COMMIT();
                }
                {
                    const int d0 = ci << 6;
                    char* xs = smem + XOFF(s);
                    #pragma unroll
                    for (int i = 0; i < 16; i++){
                        int idx = tp + (i << 7);
                        int r = idx >> 4, c4 = idx & 15;
                        float4 v = *(const float4*)(x + (size_t)(row0 + r)*DL + d0 + (c4 << 2));
                        uint2 p2;
                        p2.x = pack2h(__float2half(v.x), __float2half(v.y));
                        p2.y = pack2h(__float2half(v.z), __float2half(v.w));
                        *(uint2*)(xs + r*(XPITCH*2) + (c4 << 3)) = p2;
                    }
                }
                CPA_WAIT0();
                MBAR_ARRIVE(f1 + s*8);
            }
        } else {
            const int warp = tid >> 5, lane = tid & 31;
            const int wm = warp >> 1, wn = warp & 1;
            const int lrow = lane & 15;
            const int lcol = (lane >> 4) << 3;

            float acc[2][12][4];
            #pragma unroll
            for (int i = 0; i < 2; i++)
                #pragma unroll
                for (int j = 0; j < 12; j++)
                    #pragma unroll
                    for (int q = 0; q < 4; q++) acc[i][j][q] = 0.f;

            for (int ci = 0; ci < 16; ci++){
                const int s = ci & 1;
                const uint32_t ph = (ci >> 1) & 1;
                mbar_wait(f1 + s*8, ph);
                __half* xs = (__half*)(smem + XOFF(s));
                __half* As = (__half*)(smem + AOFF(s));
                #pragma unroll
                for (int ks = 0; ks < 4; ks++){
                    uint32_t ah[2][4];
                    #pragma unroll
                    for (int mt = 0; mt < 2; mt++){
                        int off = (wm*32 + mt*16 + lrow)*XPITCH + ks*16 + lcol;
                        ldsm4(ah[mt], xs + off);
                    }
                    uint32_t g[6][4];
                    #pragma unroll
                    for (int pp = 0; pp < 6; pp++){
                        int off = (ks*16 + lrow)*APITCH + wn*96 + pp*16 + lcol;
                        ldsm4t(g[pp], As + off);
                    }
                    #pragma unroll
                    for (int pp = 0; pp < 6; pp++)
                        #pragma unroll
                        for (int mt = 0; mt < 2; mt++){
                            mma_f16(acc[mt][2*pp],   ah[mt], g[pp]);
                            mma_f16(acc[mt][2*pp+1], ah[mt], g[pp] + 2);
                        }
                }
                MBAR_ARRIVE(e1 + s*8);
            }

            // write t1 (fp16) to global
            #pragma unroll
            for (int mt = 0; mt < 2; mt++){
                int r0w = wm*32 + mt*16 + (lane >> 2);
                #pragma unroll
                for (int nt = 0; nt < 12; nt++){
                    int c0 = wn*96 + nt*8 + ((lane & 3) << 1);
                    *(uint32_t*)((char*)g_t1 + ((size_t)(row0 + r0w)*NJ + c0)*2) =
                        pack2h(__float2half(acc[mt][nt][0]), __float2half(acc[mt][nt][1]));
                    *(uint32_t*)((char*)g_t1 + ((size_t)(row0 + r0w + 8)*NJ + c0)*2) =
                        pack2h(__float2half(acc[mt][nt][2]), __float2half(acc[mt][nt][3]));
                }
            }
            asm volatile("bar.sync 1, 256;" ::: "memory");
            __threadfence();
            if (tid == 0)
                asm volatile("red.release.gpu.global.add.s32 [%0], 1;"
                             :: "l"(&t1_ready[bid]) : "memory");
        }
        __syncthreads();   // stage transition: stage-1 smem dead
    }

    // ===== stage 2: 384 jobs over all 148 CTAs =============================
    if (tid >= 256){
        const int tp = tid - 256;
        prod_wait(&c_G, NP0);
        int tt = 0;
        for (int q = 0; ; q++){
            int j = bid + q*NCTA;
            if (j >= NJOBS2) break;
            int rt = j/3, kq = j%3;
            prod_wait(&t1_ready[rt], 1);
            mbar_wait(t1e, (q & 1) ^ 1);
            // t1 slice [128][64]h
            #pragma unroll
            for (int i = 0; i < 8; i++){
                int jj = tp + (i << 7);
                int r = jj >> 3, c = jj & 7;
                cpa16(sbase + r*144 + c*16,
                      (const char*)g_t1 + ((size_t)(rt*128 + r)*NJ + kq*64)*2 + c*16);
            }
            CPA_COMMIT();
            CPA_WAIT0();
            MBAR_ARRIVE(t1f);
            for (int nt = 0; nt < 8; nt++){
                int s = tt % 3;
                uint32_t ph = (uint32_t)((tt / 3) & 1);
                mbar_wait(e2 + s*8, ph ^ 1);
                const int e0 = nt << 7;
                uint32_t dst = sbase + GOFF(s);
                #pragma unroll
                for (int i = 0; i < 8; i++){
                    int jj = tp + (i << 7);
                    int r = jj >> 4, c = jj & 15;
                    cpa16(dst + r*272 + c*16,
                          (const char*)g_G + ((size_t)(kq*64 + r)*DL + e0)*2 + c*16);
                }
                CPA_COMMIT();
                CPA_WAIT0();
                MBAR_ARRIVE(f2 + s*8);
                tt++;
            }
        }
    } else {
        const int warp = tid >> 5, lane = tid & 31;
        const int wm = warp >> 1, wn = warp & 1;
        const int lrow = lane & 15;
        const int lcol = (lane >> 4) << 3;
        __half* t1s = (__half*)smem;

        int tt = 0;
        float acc2[2][8][4];
        for (int q = 0; ; q++){
            int j = bid + q*NCTA;
            if (j >= NJOBS2) break;
            int rt = j/3, kq = j%3;
            mbar_wait(t1f, q & 1);
            for (int nt = 0; nt < 8; nt++){
                int s = tt % 3;
                uint32_t ph = (uint32_t)((tt / 3) & 1);
                mbar_wait(f2 + s*8, ph);

                #pragma unroll
                for (int i = 0; i < 2; i++)
                    #pragma unroll
                    for (int jj = 0; jj < 8; jj++)
                        #pragma unroll
                        for (int qq = 0; qq < 4; qq++) acc2[i][jj][qq] = 0.f;

                __half* Gs = (__half*)(smem + GOFF(s));
                #pragma unroll
                for (int ks = 0; ks < 4; ks++){
                    uint32_t th[2][4];
                    #pragma unroll
                    for (int mt = 0; mt < 2; mt++){
                        int off = (wm*32 + mt*16 + lrow)*XPITCH + ks*16 + lcol;
                        ldsm4(th[mt], t1s + off);
                    }
                    uint32_t g2[4][4];
                    #pragma unroll
                    for (int pp = 0; pp < 4; pp++){
                        int off = (ks*16 + lrow)*GPITCH + wn*64 + pp*16 + lcol;
                        ldsm4t(g2[pp], Gs + off);
                    }
                    #pragma unroll
                    for (int pp = 0; pp < 4; pp++)
                        #pragma unroll
                        for (int mt = 0; mt < 2; mt++){
                            mma_f16(acc2[mt][2*pp],   th[mt], g2[pp]);
                            mma_f16(acc2[mt][2*pp+1], th[mt], g2[pp] + 2);
                        }
                }
                MBAR_ARRIVE(e2 + s*8);

                const int e0 = nt << 7;
                #pragma unroll
                for (int mt = 0; mt < 2; mt++){
                    int rr = rt*128 + wm*32 + mt*16 + (lane >> 2);
                    int cb = kq*1024 + e0 + wn*64 + ((lane & 3) << 1);
                    #pragma unroll
                    for (int ntt = 0; ntt < 8; ntt++){
                        float2 v01 = make_float2(acc2[mt][ntt][0], acc2[mt][ntt][1]);
                        float2 v23 = make_float2(acc2[mt][ntt][2], acc2[mt][ntt][3]);
                        *(float2*)(out + (size_t)rr*DOUT + cb + ntt*8)       = v01;
                        *(float2*)(out + (size_t)(rr + 8)*DOUT + cb + ntt*8) = v23;
                    }
                }
                tt++;
            }
            MBAR_ARRIVE(t1e);
        }
    }
}

// ------------------------- launch ------------------------------------------
extern "C" void kernel_launch(void* const* d_in, const int* in_sizes, int n_in,
                              void* d_out, int out_size){
    const float* x = (const float*)d_in[0];
    const float* W = (const float*)d_in[1];
    const float* A = (const float*)d_in[2];
    const float* B = (const float*)d_in[3];
    for (int i = 0; i < n_in; i++){
        switch (in_sizes[i]){
            case 16777216: x = (const float*)d_in[i]; break;   // [2,8192,1024]
            case 1769472:  W = (const float*)d_in[i]; break;   // [2304,768]
            case 196608:   A = (const float*)d_in[i]; break;   // [3,1024,64]
            case 147456:   B = (const float*)d_in[i]; break;   // [3,64,768]
            default: break;
        }
    }
    float* out = (float*)d_out;

    cudaFuncSetAttribute(qkv_main, cudaFuncAttributeMaxDynamicSharedMemorySize, SMEM_BYTES);
    qkv_main<<<NCTA, NTHR, SMEM_BYTES>>>(x, W, A, B, out);
}

// round 16
// speedup vs baseline: 1.5551x; 1.5551x over previous
#include <cuda_runtime.h>
#include <cuda_fp16.h>
#include <cstdint>

// ---------------------------------------------------------------------------
// QKVProjectedLinear, single-launch (r14 architecture + U-overlap + t1 hoist):
//   U = B @ Ws^T : CTAs 0..143, warps 0-7 only (overlapped with producer fill)
//   V/G on tail CTAs 128..147
//   stage 1: t1 = fp16(x) @ fp16(A_all)  (workers 0..127, smem-resident t1)
//   stage 2: out_k = fp16(t1_k) @ fp16(G_k), t1 fragments hoisted per kq
// 148 CTAs x 384 thr. warps 0-7 consumers, 8-11 producers.
// ---------------------------------------------------------------------------

#define K3 3
#define DL 1024
#define DS 768
#define RK 64
#define NJ 192
#define DOUT 3072
#define NWORK 128
#define NCTA 148
#define NU 144
#define NP0 20
#define NTHR 384

// ------------------------- device scratch ----------------------------------
__device__ __align__(16) float g_U[K3*RK*DS];
__device__ __align__(16) float g_Vp[K3*4*RK*RK];
__device__ __align__(16) __half g_Af[DL*NJ];             // A_all fp16 [1024,192]
__device__ __align__(16) __half g_G[K3*RK*DL];           // G fp16 [3,64,1024]
__device__ int c_A, c_U, c_V, c_G;

__device__ __forceinline__ uint32_t pack2h(__half a, __half b){
    __half2 t; t.x = a; t.y = b;
    return *reinterpret_cast<uint32_t*>(&t);
}

// ------------------------- sync helpers ------------------------------------
__device__ __forceinline__ void flag_inc(int* f){
    __syncthreads();
    __threadfence();
    if (threadIdx.x == 0)
        asm volatile("red.release.gpu.global.add.s32 [%0], 1;" :: "l"(f) : "memory");
}
__device__ __forceinline__ void flag_wait(int* f, int thr){   // CTA-wide
    if (threadIdx.x == 0){
        int v;
        do {
            asm volatile("ld.acquire.gpu.global.s32 %0, [%1];" : "=r"(v) : "l"(f));
            if (v < thr) __nanosleep(128);
        } while (v < thr);
    }
    __syncthreads();
}
__device__ __forceinline__ void prod_wait(const int* f, int thr){ // producer warps
    if (threadIdx.x == 256){
        int v;
        do {
            asm volatile("ld.acquire.gpu.global.s32 %0, [%1];" : "=r"(v) : "l"(f));
            if (v < thr) __nanosleep(128);
        } while (v < thr);
    }
    asm volatile("bar.sync 2, 128;" ::: "memory");
}

__device__ __forceinline__ uint32_t smem_u32(const void* p){
    uint32_t a;
    asm("{ .reg .u64 t; cvta.to.shared.u64 t, %1; cvt.u32.u64 %0, t; }" : "=r"(a) : "l"(p));
    return a;
}
#define MBAR_INIT(mb, c)  asm volatile("mbarrier.init.shared.b64 [%0], %1;" :: "r"(mb), "r"(c) : "memory")
#define MBAR_ARRIVE(mb)   asm volatile("mbarrier.arrive.shared.b64 _, [%0];" :: "r"(mb) : "memory")
__device__ __forceinline__ void mbar_wait(uint32_t mb, uint32_t parity){
    asm volatile(
        "{\n\t.reg .pred P;\n\t"
        "W%=:\n\t"
        "mbarrier.try_wait.parity.acquire.cta.shared::cta.b64 P, [%0], %1, 0x989680;\n\t"
        "@!P bra W%=;\n\t}"
        :: "r"(mb), "r"(parity) : "memory");
}

__device__ __forceinline__ void cpa16(uint32_t dst, const void* src){
    asm volatile("cp.async.cg.shared.global [%0], [%1], 16;" :: "r"(dst), "l"(src) : "memory");
}
#define CPA_COMMIT() asm volatile("cp.async.commit_group;" ::: "memory")
#define CPA_WAIT0()  asm volatile("cp.async.wait_group 0;" ::: "memory")
#define BAR3()       asm volatile("bar.sync 3, 256;" ::: "memory")

// ------------------------- mma helpers --------------------------------------
__device__ __forceinline__ void ldsm4(uint32_t* r, const void* p){
    uint32_t a = smem_u32(p);
    asm volatile("ldmatrix.sync.aligned.m8n8.x4.shared.b16 {%0,%1,%2,%3}, [%4];"
        : "=r"(r[0]), "=r"(r[1]), "=r"(r[2]), "=r"(r[3]) : "r"(a));
}
__device__ __forceinline__ void ldsm4t(uint32_t* r, const void* p){
    uint32_t a = smem_u32(p);
    asm volatile("ldmatrix.sync.aligned.m8n8.x4.trans.shared.b16 {%0,%1,%2,%3}, [%4];"
        : "=r"(r[0]), "=r"(r[1]), "=r"(r[2]), "=r"(r[3]) : "r"(a));
}
__device__ __forceinline__ void mma_f16(float* c, const uint32_t* a, const uint32_t* b){
    asm volatile("mma.sync.aligned.m16n8k16.row.col.f32.f16.f16.f32 "
        "{%0,%1,%2,%3}, {%4,%5,%6,%7}, {%8,%9}, {%0,%1,%2,%3};"
        : "+f"(c[0]), "+f"(c[1]), "+f"(c[2]), "+f"(c[3])
        : "r"(a[0]), "r"(a[1]), "r"(a[2]), "r"(a[3]), "r"(b[0]), "r"(b[1]));
}

// ------------------------- smem layout --------------------------------------
// stage1: x bufs [s] 2x18432 @0; A bufs [s] 2x25600 @36864 (end 88064)
// U scratch (overlapped with stage1): [64][65]+[16][65] fl = 20800 @51200? NO -
//   U scratch @ 51200 overlaps A buf 0 tail!  AOFF(0)=36864..62464.
//   Use @ 62464 (A buf1 is 62464..88064) — also conflict.  Put U at 88064:
//   88064 + 20800 = 108864 -> grow smem.  (region unused by stage1)
// stage2: t1 [128][200]h 51200 @0; G bufs [s] 3x17408 @51200 (end 103424)
#define XOFF(s)     ((s)*18432)
#define AOFF(s)     (36864 + (s)*25600)
#define T1_OFF      0
#define GOFF(s)     (51200 + (s)*17408)
#define U_OFF       88064
#define SMEM_BYTES  108864
#define XPITCH 72
#define APITCH 200
#define TPITCH 200
#define GPITCH 136

// ------------------------- phase-0 jobs -------------------------------------
// U[k,r,s] = sum_t B[k,r,t]*W[(k*768+s),t].  Job: 64 rows x 16 s-cols.
// 256-thread variant (warps 0-7): loads by 256, compute by warps 0-3, bar3.
__device__ void p0U16_job256(int k, int s0, char* smem,
                             const float* __restrict__ B, const float* __restrict__ W){
    float* Bt = (float*)(smem + U_OFF);   // [64][65]
    float* Wt = Bt + 64*65;               // [16][65]
    const int tid = threadIdx.x;          // < 256
    const int lane = tid & 31, w = tid >> 5;
    float acc[2][4] = {};
    for (int tc = 0; tc < 12; tc++){
        const int t0 = tc*64;
        BAR3();
        #pragma unroll
        for (int i = 0; i < 16; i++){
            int idx = tid + (i<<8);
            int r = idx >> 6, t = idx & 63;
            Bt[r*65 + t] = B[(k*64 + r)*DS + t0 + t];
        }
        #pragma unroll
        for (int i = 0; i < 4; i++){
            int idx = tid + (i<<8);
            int s = idx >> 6, t = idx & 63;
            Wt[s*65 + t] = W[(size_t)(k*DS + s0 + s)*DS + t0 + t];
        }
        BAR3();
        if (w < 4){
            #pragma unroll 8
            for (int t = 0; t < 64; t++){
                float a0 = Bt[lane*65 + t];
                float a1 = Bt[(lane + 32)*65 + t];
                #pragma unroll
                for (int j = 0; j < 4; j++){
                    float b = Wt[(w*4 + j)*65 + t];
                    acc[0][j] += a0*b;
                    acc[1][j] += a1*b;
                }
            }
        }
    }
    if (w < 4){
        #pragma unroll
        for (int j = 0; j < 4; j++){
            g_U[(k*64 + lane)*DS + s0 + w*4 + j]      = acc[0][j];
            g_U[(k*64 + lane + 32)*DS + s0 + w*4 + j] = acc[1][j];
        }
    }
    BAR3();
    __threadfence();
    if (tid == 0)
        asm volatile("red.release.gpu.global.add.s32 [%0], 1;" :: "l"(&c_U) : "memory");
}

__device__ void p0V_job(int k, int sc, char* smem, const float* __restrict__ B){
    float* Us = (float*)smem;          // [64][65]
    float* Bs = Us + 64*65;
    int tid = threadIdx.x;
    float acc[4][4] = {};
    int r0 = (tid & 15)*4, q0 = ((tid >> 4) & 15)*4;
    for (int si = 0; si < 3; si++){
        int s0 = sc*192 + si*64;
        __syncthreads();
        if (tid < 256){
            #pragma unroll
            for (int i = 0; i < 16; i++){
                int idx = tid + (i<<8); int r = idx>>6, s = idx&63;
                Us[r*65 + s] = g_U[(k*64 + r)*DS + s0 + s];
                Bs[r*65 + s] = B[(k*64 + r)*DS + s0 + s];
            }
        }
        __syncthreads();
        if (tid < 256){
            #pragma unroll 4
            for (int s = 0; s < 64; s++){
                float a[4], b[4];
                #pragma unroll
                for (int i = 0; i < 4; i++){ a[i] = Us[(r0+i)*65 + s]; b[i] = Bs[(q0+i)*65 + s]; }
                #pragma unroll
                for (int i = 0; i < 4; i++)
                    #pragma unroll
                    for (int j = 0; j < 4; j++) acc[i][j] += a[i]*b[j];
            }
        }
    }
    if (tid < 256)
        #pragma unroll
        for (int i = 0; i < 4; i++)
            #pragma unroll
            for (int j = 0; j < 4; j++)
                g_Vp[((k*4 + sc)*64 + r0 + i)*64 + q0 + j] = acc[i][j];
    __syncthreads();
}

__device__ void p0G_job(int k, int e0, char* smem, const float* __restrict__ A){
    float* Vs = (float*)smem;          // [64][68]
    float* As = Vs + 64*68;
    int tid = threadIdx.x;
    __syncthreads();
    if (tid < 256){
        #pragma unroll
        for (int i = 0; i < 16; i++){
            int idx = tid + (i<<8); int a = idx>>6, b = idx&63;
            float v = 0.f;
            #pragma unroll
            for (int sc = 0; sc < 4; sc++) v += g_Vp[((k*4 + sc)*64 + a)*64 + b];
            Vs[a*68 + b] = v;
            As[a*68 + b] = A[(size_t)(k*DL + e0 + a)*RK + b];
        }
    }
    __syncthreads();
    if (tid < 256){
        int r0 = (tid & 15)*4, ee = ((tid >> 4) & 15)*4;
        float acc[4][4] = {};
        #pragma unroll 4
        for (int q = 0; q < 64; q++){
            float a[4], b[4];
            #pragma unroll
            for (int i = 0; i < 4; i++){ a[i] = Vs[(r0+i)*68 + q]; b[i] = As[(ee+i)*68 + q]; }
            #pragma unroll
            for (int i = 0; i < 4; i++)
                #pragma unroll
                for (int j = 0; j < 4; j++) acc[i][j] += a[i]*b[j];
        }
        #pragma unroll
        for (int i = 0; i < 4; i++)
            #pragma unroll
            for (int j = 0; j < 4; j++)
                g_G[(size_t)(k*64 + r0 + i)*DL + e0 + ee + j] = __float2half(acc[i][j]);
    }
    __syncthreads();
}

__global__ __launch_bounds__(NTHR, 1)
void qkv_main(const float* __restrict__ x, const float* __restrict__ W,
              const float* __restrict__ A, const float* __restrict__ B,
              float* __restrict__ out){
    extern __shared__ char smem[];
    __shared__ __align__(8) uint64_t s_mb[10];  // f1[2] e1[2] f2[3] e2[3]

    const int tid = threadIdx.x;
    const int bid = blockIdx.x;
    const uint32_t sbase = smem_u32(smem);
    const uint32_t f1 = smem_u32(&s_mb[0]);
    const uint32_t e1 = smem_u32(&s_mb[2]);
    const uint32_t f2 = smem_u32(&s_mb[4]);
    const uint32_t e2 = smem_u32(&s_mb[7]);

    if (tid == 0){
        MBAR_INIT(f1,     128); MBAR_INIT(f1 + 8, 128);
        MBAR_INIT(e1,     256); MBAR_INIT(e1 + 8, 256);
        MBAR_INIT(f2,     128); MBAR_INIT(f2 + 8, 128); MBAR_INIT(f2 + 16, 128);
        MBAR_INIT(e2,     256); MBAR_INIT(e2 + 8, 256); MBAR_INIT(e2 + 16, 256);
    }
    __syncthreads();

    // ===== phase 0a: A conversion (all CTAs, all threads) ==================
    for (int idx = bid*NTHR + tid; idx < K3*DL*RK; idx += NCTA*NTHR){
        int k = idx/(DL*RK); int rem = idx%(DL*RK); int d = rem/RK; int r = rem%RK;
        g_Af[d*NJ + k*RK + r] = __float2half(A[idx]);
    }
    flag_inc(&c_A);

    if (bid >= NWORK){
        // ===== tail CTAs: U (warps 0-7), then V, then G ====================
        if (bid < NU && tid < 256)
            p0U16_job256(bid/48, (bid%48)*16, smem, B, W);
        const int p = bid - NWORK;     // 0..19
        flag_wait(&c_U, NU);
        if (p < 12){
            p0V_job(p/4, p%4, smem, B);
            flag_inc(&c_V);
        }
        flag_wait(&c_V, 12);
        for (int j = p; j < 48; j += NP0)
            p0G_job(j/16, (j%16)*64, smem, A);
        flag_inc(&c_G);
        return;
    }

    // ===== worker CTAs =====================================================
    const int row0 = bid * 128;

    if (tid >= 256){
        // ==================== PRODUCER (warps 8-11) ========================
        // starts immediately — overlaps with U on warps 0-7
        const int tp = tid - 256;
        prod_wait(&c_A, NCTA);
        for (int ci = 0; ci < 16; ci++){
            const int s = ci & 1;
            const uint32_t ph = (ci >> 1) & 1;
            mbar_wait(e1 + s*8, ph ^ 1);
            {
                const char* src = (const char*)g_Af + (size_t)ci*24576;
                uint32_t dst = sbase + AOFF(s);
                #pragma unroll
                for (int i = 0; i < 12; i++){
                    int j = tp + (i << 7);
                    int r = j / 24, c = j % 24;
                    cpa16(dst + r*400 + c*16, src + j*16);
                }
                CPA_COMMIT();
            }
            {
                const int d0 = ci << 6;
                char* xs = smem + XOFF(s);
                #pragma unroll
                for (int i = 0; i < 16; i++){
                    int idx = tp + (i << 7);
                    int r = idx >> 4, c4 = idx & 15;
                    float4 v = *(const float4*)(x + (size_t)(row0 + r)*DL + d0 + (c4 << 2));
                    uint2 p2;
                    p2.x = pack2h(__float2half(v.x), __float2half(v.y));
                    p2.y = pack2h(__float2half(v.z), __float2half(v.w));
                    *(uint2*)(xs + r*(XPITCH*2) + (c4 << 3)) = p2;
                }
            }
            CPA_WAIT0();
            MBAR_ARRIVE(f1 + s*8);
        }
        prod_wait(&c_G, NP0);
        __syncthreads();                       // stage transition
        for (int t = 0; t < 24; t++){
            const int s = t % 3;
            const uint32_t ph = (uint32_t)((t / 3) & 1);
            mbar_wait(e2 + s*8, ph ^ 1);
            const int kq = t >> 3, nt = t & 7;
            const int e0 = nt << 7;
            uint32_t dst = sbase + GOFF(s);
            #pragma unroll
            for (int i = 0; i < 8; i++){
                int j = tp + (i << 7);
                int r = j >> 4, c = j & 15;
                cpa16(dst + r*272 + c*16,
                      (const char*)g_G + ((size_t)(kq*64 + r)*DL + e0)*2 + c*16);
            }
            CPA_COMMIT();
            CPA_WAIT0();
            MBAR_ARRIVE(f2 + s*8);
        }
        return;
    }

    // ======================= CONSUMER (warps 0-7) ==========================
    // U job first (overlapped with producer prefill), then stage-1 mma.
    p0U16_job256(bid/48, (bid%48)*16, smem, B, W);

    const int warp = tid >> 5, lane = tid & 31;
    const int wm = warp >> 1, wn = warp & 1;
    const int lrow = lane & 15;
    const int lcol = (lane >> 4) << 3;

    __half* t1s = (__half*)(smem + T1_OFF);

    float acc[2][12][4];
    #pragma unroll
    for (int i = 0; i < 2; i++)
        #pragma unroll
        for (int j = 0; j < 12; j++)
            #pragma unroll
            for (int q = 0; q < 4; q++) acc[i][j][q] = 0.f;

    for (int ci = 0; ci < 16; ci++){
        const int s = ci & 1;
        const uint32_t ph = (ci >> 1) & 1;
        mbar_wait(f1 + s*8, ph);
        __half* xs = (__half*)(smem + XOFF(s));
        __half* As = (__half*)(smem + AOFF(s));
        #pragma unroll
        for (int ks = 0; ks < 4; ks++){
            uint32_t ah[2][4];
            #pragma unroll
            for (int mt = 0; mt < 2; mt++){
                int off = (wm*32 + mt*16 + lrow)*XPITCH + ks*16 + lcol;
                ldsm4(ah[mt], xs + off);
            }
            uint32_t g[6][4];
            #pragma unroll
            for (int pp = 0; pp < 6; pp++){
                int off = (ks*16 + lrow)*APITCH + wn*96 + pp*16 + lcol;
                ldsm4t(g[pp], As + off);
            }
            #pragma unroll
            for (int pp = 0; pp < 6; pp++)
                #pragma unroll
                for (int mt = 0; mt < 2; mt++){
                    mma_f16(acc[mt][2*pp],   ah[mt], g[pp]);
                    mma_f16(acc[mt][2*pp+1], ah[mt], g[pp] + 2);
                }
        }
        MBAR_ARRIVE(e1 + s*8);
    }

    // consumers done reading x/A before t1 overwrite
    asm volatile("bar.sync 1, 256;" ::: "memory");

    // spill t1 (single fp16) into [0,51200)
    #pragma unroll
    for (int mt = 0; mt < 2; mt++){
        int r0w = wm*32 + mt*16 + (lane >> 2);
        #pragma unroll
        for (int nt = 0; nt < 12; nt++){
            int c0 = wn*96 + nt*8 + ((lane & 3) << 1);
            *(uint32_t*)(t1s + r0w*TPITCH + c0) =
                pack2h(__float2half(acc[mt][nt][0]), __float2half(acc[mt][nt][1]));
            *(uint32_t*)(t1s + (r0w+8)*TPITCH + c0) =
                pack2h(__float2half(acc[mt][nt][2]), __float2half(acc[mt][nt][3]));
        }
    }
    __syncthreads();                           // stage transition (with producers)

    // ===== stage 2: t1 fragments hoisted per kq ============================
    float acc2[2][8][4];
    int tt = 0;
    for (int kq = 0; kq < 3; kq++){
        uint32_t th[4][2][4];
        #pragma unroll
        for (int ks = 0; ks < 4; ks++)
            #pragma unroll
            for (int mt = 0; mt < 2; mt++){
                int off = (wm*32 + mt*16 + lrow)*TPITCH + kq*64 + ks*16 + lcol;
                ldsm4(th[ks][mt], t1s + off);
            }
        for (int nt = 0; nt < 8; nt++){
            int s = tt % 3;
            uint32_t ph = (uint32_t)((tt / 3) & 1);
            mbar_wait(f2 + s*8, ph);

            #pragma unroll
            for (int i = 0; i < 2; i++)
                #pragma unroll
                for (int j = 0; j < 8; j++)
                    #pragma unroll
                    for (int q = 0; q < 4; q++) acc2[i][j][q] = 0.f;

            __half* Gs = (__half*)(smem + GOFF(s));
            #pragma unroll
            for (int ks = 0; ks < 4; ks++){
                uint32_t g2[4][4];
                #pragma unroll
                for (int pp = 0; pp < 4; pp++){
                    int off = (ks*16 + lrow)*GPITCH + wn*64 + pp*16 + lcol;
                    ldsm4t(g2[pp], Gs + off);
                }
                #pragma unroll
                for (int pp = 0; pp < 4; pp++)
                    #pragma unroll
                    for (int mt = 0; mt < 2; mt++){
                        mma_f16(acc2[mt][2*pp],   th[ks][mt], g2[pp]);
                        mma_f16(acc2[mt][2*pp+1], th[ks][mt], g2[pp] + 2);
                    }
            }
            MBAR_ARRIVE(e2 + s*8);

            const int e0 = nt << 7;
            #pragma unroll
            for (int mt = 0; mt < 2; mt++){
                int rr = row0 + wm*32 + mt*16 + (lane >> 2);
                int cb = kq*1024 + e0 + wn*64 + ((lane & 3) << 1);
                #pragma unroll
                for (int ntt = 0; ntt < 8; ntt++){
                    float2 v01 = make_float2(acc2[mt][ntt][0], acc2[mt][ntt][1]);
                    float2 v23 = make_float2(acc2[mt][ntt][2], acc2[mt][ntt][3]);
                    *(float2*)(out + (size_t)rr*DOUT + cb + ntt*8)       = v01;
                    *(float2*)(out + (size_t)(rr + 8)*DOUT + cb + ntt*8) = v23;
                }
            }
            tt++;
        }
    }
}

// ------------------------- launch ------------------------------------------
extern "C" void kernel_launch(void* const* d_in, const int* in_sizes, int n_in,
                              void* d_out, int out_size){
    const float* x = (const float*)d_in[0];
    const float* W = (const float*)d_in[1];
    const float* A = (const float*)d_in[2];
    const float* B = (const float*)d_in[3];
    for (int i = 0; i < n_in; i++){
        switch (in_sizes[i]){
            case 16777216: x = (const float*)d_in[i]; break;   // [2,8192,1024]
            case 1769472:  W = (const float*)d_in[i]; break;   // [2304,768]
            case 196608:   A = (const float*)d_in[i]; break;   // [3,1024,64]
            case 147456:   B = (const float*)d_in[i]; break;   // [3,64,768]
            default: break;
        }
    }
    float* out = (float*)d_out;

    cudaFuncSetAttribute(qkv_main, cudaFuncAttributeMaxDynamicSharedMemorySize, SMEM_BYTES);
    qkv_main<<<NCTA, NTHR, SMEM_BYTES>>>(x, W, A, B, out);
}